// round 14
// baseline (speedup 1.0000x reference)
#include <cuda_runtime.h>
#include <cstdint>

#define TASKS   128
#define NSAMP   2048
#define INDIM   256
#define OUTDIM  256
#define APITCH  260                 // %32==4 -> conflict-free A frags
#define BPITCH  136                 // %32==8 -> conflict-free B frags
#define KCH     16
#define NBUF    4
#define AHI_OFF 0
#define ALO_OFF (16 * APITCH * 4)
#define B_OFF   (2 * 16 * APITCH * 4)
#define BBUF_B  (KCH * BPITCH * 4)
#define DYN_BYTES (B_OFF + NBUF * BBUF_B + 16)

__device__ __forceinline__ unsigned smem_u32(const void* p) {
    unsigned r;
    asm("{ .reg .u64 t; cvta.to.shared.u64 t, %1; cvt.u32.u64 %0, t; }" : "=r"(r) : "l"(p));
    return r;
}
__device__ __forceinline__ float tf32r(float x) {
    unsigned u;
    asm("cvt.rna.tf32.f32 %0, %1;" : "=r"(u) : "f"(x));
    return __uint_as_float(u);
}
__device__ __forceinline__ void mma8(float (&d)[4], const unsigned (&a)[4],
                                     unsigned b0, unsigned b1) {
    asm volatile(
        "mma.sync.aligned.m16n8k8.row.col.f32.tf32.tf32.f32 "
        "{%0,%1,%2,%3},{%4,%5,%6,%7},{%8,%9},{%0,%1,%2,%3};"
        : "+f"(d[0]), "+f"(d[1]), "+f"(d[2]), "+f"(d[3])
        : "r"(a[0]), "r"(a[1]), "r"(a[2]), "r"(a[3]), "r"(b0), "r"(b1));
}
#define CP16(dst, src) \
    asm volatile("cp.async.cg.shared.global [%0], [%1], 16;" :: "r"(dst), "l"(src) : "memory")
#define CP_COMMIT() asm volatile("cp.async.commit_group;" ::: "memory")
#define CP_WAIT3()  asm volatile("cp.async.wait_group 3;" ::: "memory")
#define CP_WAIT0()  asm volatile("cp.async.wait_group 0;" ::: "memory")

// B chunk (16 k-rows x 128 cols of this half) issued by warps 4-7 (tid 128..255)
__device__ __forceinline__ void issueB(const float* __restrict__ Wt, unsigned bbase,
                                       int kc, int tid, int half) {
    if (tid < 128) return;
    const int t = tid - 128;
    const int row = t >> 3, cg = t & 7;           // 16 rows x 8 groups of 16 floats
    const float* src = Wt + (size_t)(kc * KCH + row) * OUTDIM + half * 128 + cg * 16;
    const unsigned dst = bbase + (unsigned)(row * BPITCH + cg * 16) * 4u;
    #pragma unroll
    for (int u = 0; u < 4; ++u)
        CP16(dst + 16u * (unsigned)u, src + 4 * u);
}

__global__ __launch_bounds__(256, 3)
void tsl_mma(const float* __restrict__ X, const void* __restrict__ TIDS,
             const float* __restrict__ W, float* __restrict__ OUT)
{
    extern __shared__ __align__(16) char dyn[];
    __shared__ unsigned short sl[96];
    __shared__ int s_cnt;

    const int tid = threadIdx.x, wid = tid >> 5, lane = tid & 31;
    const int l4 = lane >> 2, lm = lane & 3;
    const int b    = blockIdx.x;
    const int g    = b >> 8;                       // 0..3 (g=0 first: real work starts early)
    const int task = (b & 255) >> 1;
    const int half = b & 1;
    const int glo  = g * 16;

    const float* Wt = W + (size_t)task * INDIM * OUTDIM;
    const unsigned bbase0 = smem_u32(dyn + B_OFF);

    // ---- warps 4-7: prefetch first 4 B chunks while warp 0 scans ----
    #pragma unroll
    for (int c = 0; c < NBUF; ++c) {
        issueB(Wt, bbase0 + (unsigned)c * BBUF_B, c, tid, half);
        CP_COMMIT();
    }

    // ---- warp 0: ballot scan for this task's samples [glo, ghi) ----
    if (wid == 0) {
        const unsigned* w32 = (const unsigned*)TIDS;
        const unsigned v = w32[2 * lane + 1] | w32[2 * (lane + 32) + 1];
        const bool is64 = !__any_sync(0xffffffffu, v != 0);  // int64 iff hi words all 0
        const int hi = (g == 3) ? 96 : glo + 16;
        int base = 0;
        #pragma unroll 1
        for (int rb = 0; rb < 8; ++rb) {
            int ids[8];
            #pragma unroll
            for (int j = 0; j < 8; ++j) {
                const int n = (rb * 8 + j) * 32 + lane;
                ids[j] = is64 ? (int)w32[2 * n] : (int)w32[n];
            }
            #pragma unroll
            for (int j = 0; j < 8; ++j) {
                const bool m = (ids[j] == task);
                const unsigned bal = __ballot_sync(0xffffffffu, m);
                if (m) {
                    const int pos = base + __popc(bal & ((1u << lane) - 1u));
                    if (pos >= glo && pos < hi)
                        sl[pos - glo] = (unsigned short)((rb * 8 + j) * 32 + lane);
                }
                base += __popc(bal);
            }
        }
        if (lane == 0) s_cnt = base;
    }
    __syncthreads();
    const int cnt = s_cnt;
    if (cnt <= glo) { CP_WAIT0(); return; }        // empty group -> fast exit

    float* Ah = (float*)(dyn + AHI_OFF);
    float* Al = (float*)(dyn + ALO_OFF);
    const int gend = (g == 3) ? ((cnt < 96) ? cnt : 96) : ((cnt < glo + 16) ? cnt : glo + 16);

    #pragma unroll 1
    for (int m0 = glo; m0 < gend; m0 += 16) {
        const int slbase = m0 - glo;
        if (m0 > glo) {                            // rare overflow chunk: restream B
            #pragma unroll
            for (int c = 0; c < NBUF; ++c) {
                issueB(Wt, bbase0 + (unsigned)c * BBUF_B, c, tid, half);
                CP_COMMIT();
            }
        }

        // ---- fill A (16 rows x 256 k) tf32 hi/lo; invalid rows -> 0 ----
        {
            const int s = tid >> 4, q = tid & 15;
            const bool valid = (m0 + s < cnt);
            const unsigned srow = valid ? (unsigned)sl[slbase + s] : 0u;
            const float4* xr = (const float4*)(X + srow * INDIM) + q * 4;
            #pragma unroll
            for (int j = 0; j < 4; ++j) {
                float4 v = valid ? __ldg(xr + j) : make_float4(0.f, 0.f, 0.f, 0.f);
                float4 h = make_float4(tf32r(v.x), tf32r(v.y), tf32r(v.z), tf32r(v.w));
                float4 l = make_float4(tf32r(v.x - h.x), tf32r(v.y - h.y),
                                       tf32r(v.z - h.z), tf32r(v.w - h.w));
                const int o = s * APITCH + q * 16 + 4 * j;
                *(float4*)(Ah + o) = h;
                *(float4*)(Al + o) = l;
            }
        }
        __syncthreads();

        float cacc[2][4];
        #pragma unroll
        for (int nt = 0; nt < 2; ++nt)
            #pragma unroll
            for (int p = 0; p < 4; ++p) cacc[nt][p] = 0.f;

        #pragma unroll 1
        for (int kc = 0; kc < INDIM / KCH; ++kc) {
            CP_WAIT3();
            __syncthreads();
            const float* Bb = (const float*)(dyn + B_OFF + (kc & 3) * BBUF_B);

            #pragma unroll
            for (int h = 0; h < 2; ++h) {
                const int kl = h * 8 + lm;
                const int cb = kc * KCH + kl;

                unsigned ubh0[2], ubh1[2], ubl0[2], ubl1[2];
                #pragma unroll
                for (int nt = 0; nt < 2; ++nt) {
                    const int n = wid * 16 + nt * 8 + l4;
                    const float w0 = Bb[(kl)     * BPITCH + n];
                    const float w1 = Bb[(kl + 4) * BPITCH + n];
                    const float bh0 = tf32r(w0), bh1 = tf32r(w1);
                    ubh0[nt] = __float_as_uint(bh0);
                    ubh1[nt] = __float_as_uint(bh1);
                    ubl0[nt] = __float_as_uint(tf32r(w0 - bh0));
                    ubl1[nt] = __float_as_uint(tf32r(w1 - bh1));
                }

                unsigned ah[4], al[4];
                ah[0] = __float_as_uint(Ah[(l4)     * APITCH + cb]);
                ah[1] = __float_as_uint(Ah[(l4 + 8) * APITCH + cb]);
                ah[2] = __float_as_uint(Ah[(l4)     * APITCH + cb + 4]);
                ah[3] = __float_as_uint(Ah[(l4 + 8) * APITCH + cb + 4]);
                al[0] = __float_as_uint(Al[(l4)     * APITCH + cb]);
                al[1] = __float_as_uint(Al[(l4 + 8) * APITCH + cb]);
                al[2] = __float_as_uint(Al[(l4)     * APITCH + cb + 4]);
                al[3] = __float_as_uint(Al[(l4 + 8) * APITCH + cb + 4]);

                #pragma unroll
                for (int nt = 0; nt < 2; ++nt) {
                    mma8(cacc[nt], ah, ubh0[nt], ubh1[nt]);   // hi*hi
                    mma8(cacc[nt], al, ubh0[nt], ubh1[nt]);   // lo*hi
                    mma8(cacc[nt], ah, ubl0[nt], ubl1[nt]);   // hi*lo
                }
            }
            __syncthreads();
            if (kc + NBUF < INDIM / KCH)
                issueB(Wt, bbase0 + (unsigned)(kc & 3) * BBUF_B, kc + NBUF, tid, half);
            CP_COMMIT();
        }

        // ---- store ----
        #pragma unroll
        for (int nt = 0; nt < 2; ++nt) {
            const int col = half * 128 + wid * 16 + nt * 8 + 2 * lm;
            if (m0 + l4 < cnt)
                *(float2*)(OUT + (size_t)sl[slbase + l4] * OUTDIM + col)
                    = make_float2(cacc[nt][0], cacc[nt][1]);
            if (m0 + l4 + 8 < cnt)
                *(float2*)(OUT + (size_t)sl[slbase + l4 + 8] * OUTDIM + col)
                    = make_float2(cacc[nt][2], cacc[nt][3]);
        }
        __syncthreads();
    }
    CP_WAIT0();
}

extern "C" void kernel_launch(void* const* d_in, const int* in_sizes, int n_in,
                              void* d_out, int out_size)
{
    const float* X    = (const float*)d_in[0];
    const void*  TIDS = d_in[1];
    const float* W    = (const float*)d_in[2];
    float*       OUT  = (float*)d_out;

    cudaFuncSetAttribute(tsl_mma, cudaFuncAttributeMaxDynamicSharedMemorySize, DYN_BYTES);
    tsl_mma<<<1024, 256, DYN_BYTES>>>(X, TIDS, W, OUT);
}

// round 15
// speedup vs baseline: 1.3653x; 1.3653x over previous
#include <cuda_runtime.h>
#include <cuda_bf16.h>
#include <cstdint>

#define TASKS   128
#define NSAMP   2048
#define INDIM   256
#define OUTDIM  256
#define AP32    132                 // u32 pitch per A row (128 bf16x2 pairs + pad)
#define BPITCH  260                 // f32 pitch per B row; %32==4 -> conflict-free frags
#define KCH     16
#define NBUF    5
#define AHI_OFF 0
#define ALO_OFF (32 * AP32 * 4)
#define B_OFF   (2 * 32 * AP32 * 4)
#define BBUF_B  (KCH * BPITCH * 4)
#define DYN_BYTES (B_OFF + NBUF * BBUF_B + 16)

__device__ __forceinline__ unsigned smem_u32(const void* p) {
    unsigned r;
    asm("{ .reg .u64 t; cvta.to.shared.u64 t, %1; cvt.u32.u64 %0, t; }" : "=r"(r) : "l"(p));
    return r;
}
// pack two f32 -> bf16x2 (x0 in low half), plus exact residuals
__device__ __forceinline__ unsigned packbf(float lo, float hi) {
    unsigned r;
    asm("cvt.rn.bf16x2.f32 %0, %1, %2;" : "=r"(r) : "f"(hi), "f"(lo));
    return r;
}
__device__ __forceinline__ void split2(float x0, float x1, unsigned& h, unsigned& l) {
    h = packbf(x0, x1);
    const float h0 = __uint_as_float(h << 16);
    const float h1 = __uint_as_float(h & 0xffff0000u);
    l = packbf(x0 - h0, x1 - h1);
}
__device__ __forceinline__ void mmabf(float (&d)[4], const unsigned (&a)[4],
                                      unsigned b0, unsigned b1) {
    asm volatile(
        "mma.sync.aligned.m16n8k16.row.col.f32.bf16.bf16.f32 "
        "{%0,%1,%2,%3},{%4,%5,%6,%7},{%8,%9},{%0,%1,%2,%3};"
        : "+f"(d[0]), "+f"(d[1]), "+f"(d[2]), "+f"(d[3])
        : "r"(a[0]), "r"(a[1]), "r"(a[2]), "r"(a[3]), "r"(b0), "r"(b1));
}
#define CP16(dst, src) \
    asm volatile("cp.async.cg.shared.global [%0], [%1], 16;" :: "r"(dst), "l"(src) : "memory")
#define CP_COMMIT() asm volatile("cp.async.commit_group;" ::: "memory")
#define CP_WAIT3()  asm volatile("cp.async.wait_group 3;" ::: "memory")
#define CP_WAIT0()  asm volatile("cp.async.wait_group 0;" ::: "memory")

// warps 4-7 stream one 16-row x 256-col B chunk
__device__ __forceinline__ void issueB(const float* __restrict__ Wt, unsigned bbase,
                                       int kc, int tid) {
    if (tid >= 128) {
        const int t = tid - 128, row = t >> 3, cg = t & 7;
        const float* src = Wt + (size_t)(kc * KCH + row) * OUTDIM + cg * 32;
        const unsigned dst = bbase + (unsigned)(row * BPITCH + cg * 32) * 4u;
        #pragma unroll
        for (int u = 0; u < 8; ++u)
            CP16(dst + 16u * (unsigned)u, src + 4 * u);
    }
}

__global__ __launch_bounds__(256, 1)
void tsl_mma(const float* __restrict__ X, const void* __restrict__ TIDS,
             const float* __restrict__ W, float* __restrict__ OUT)
{
    extern __shared__ __align__(16) char dyn[];
    __shared__ unsigned short sl[NSAMP];
    __shared__ int s_cnt;
    __shared__ unsigned orv;

    const int tid = threadIdx.x, wid = tid >> 5, lane = tid & 31;
    const int g = lane >> 2, lm = lane & 3;
    const int task = blockIdx.x;
    const int nb = wid * 32;                       // warp's 32-col slice

    const float* Wt = W + (size_t)task * INDIM * OUTDIM;
    const unsigned bbase0 = smem_u32(dyn + B_OFF);

    if (tid == 0) { s_cnt = 0; orv = 0; }

    // ---- prefetch first 4 B chunks before/while scanning ----
    #pragma unroll
    for (int c = 0; c < 4; ++c) {
        issueB(Wt, bbase0 + (unsigned)c * BBUF_B, c, tid);
        CP_COMMIT();
    }
    __syncthreads();

    // ---- ballot-compress scan for this task ----
    const unsigned* w32 = (const unsigned*)TIDS;
    atomicOr(&orv, w32[2 * tid + 1]);              // int64 iff hi words (0..255) all 0
    __syncthreads();
    const bool is64 = (orv == 0);

    #pragma unroll 1
    for (int j = 0; j < 8; ++j) {
        const int n = j * 256 + tid;
        const int id = is64 ? (int)w32[2 * n] : (int)w32[n];
        const bool m = (id == task);
        const unsigned bal = __ballot_sync(0xffffffffu, m);
        if (bal) {
            int b = 0;
            if (lane == 0) b = atomicAdd(&s_cnt, __popc(bal));
            b = __shfl_sync(0xffffffffu, b, 0);
            if (m) sl[b + __popc(bal & ((1u << lane) - 1u))] = (unsigned short)n;
        }
    }
    __syncthreads();
    const int cnt = s_cnt;
    if (cnt == 0) { CP_WAIT0(); return; }

    unsigned* Ahu = (unsigned*)(dyn + AHI_OFF);
    unsigned* Alu = (unsigned*)(dyn + ALO_OFF);

    #pragma unroll 1
    for (int mc = 0; mc * 32 < cnt; ++mc) {
        if (mc > 0) {                              // rare overflow chunk: restream B
            #pragma unroll
            for (int c = 0; c < 4; ++c) {
                issueB(Wt, bbase0 + (unsigned)(c % NBUF) * BBUF_B, c, tid);
                CP_COMMIT();
            }
        }
        const bool two = (cnt - mc * 32) > 16;

        // ---- fill A: 32 rows x 256 k as packed bf16x2 hi/lo ----
        {
            const int s = tid >> 3, q = tid & 7;
            const bool valid = (mc * 32 + s < cnt);
            const unsigned srow = valid ? (unsigned)sl[mc * 32 + s] : 0u;
            const float4* xr = (const float4*)(X + srow * INDIM) + q * 8;
            #pragma unroll
            for (int j = 0; j < 8; ++j) {
                float4 v = valid ? __ldg(xr + j) : make_float4(0.f, 0.f, 0.f, 0.f);
                unsigned h0, l0, h1, l1;
                split2(v.x, v.y, h0, l0);
                split2(v.z, v.w, h1, l1);
                const int o = s * AP32 + (q * 8 + j) * 2;
                *(uint2*)(Ahu + o) = make_uint2(h0, h1);
                *(uint2*)(Alu + o) = make_uint2(l0, l1);
            }
        }
        __syncthreads();

        float cacc[2][4][4];
        #pragma unroll
        for (int mt = 0; mt < 2; ++mt)
            #pragma unroll
            for (int nt = 0; nt < 4; ++nt)
                #pragma unroll
                for (int p = 0; p < 4; ++p) cacc[mt][nt][p] = 0.f;

        #pragma unroll 1
        for (int kc = 0; kc < INDIM / KCH; ++kc) {
            CP_WAIT3();
            __syncthreads();                       // also guards buffer (kc+4)%5 reuse
            if (kc + 4 < INDIM / KCH)
                issueB(Wt, bbase0 + (unsigned)((kc + 4) % NBUF) * BBUF_B, kc + 4, tid);
            CP_COMMIT();

            const float* Bb = (const float*)(dyn + B_OFF + (kc % NBUF) * BBUF_B);
            const int ka = kc * 8 + lm;

            unsigned ah[4], al[4];
            ah[0] = Ahu[(g)     * AP32 + ka];
            ah[1] = Ahu[(g + 8) * AP32 + ka];
            ah[2] = Ahu[(g)     * AP32 + ka + 4];
            ah[3] = Ahu[(g + 8) * AP32 + ka + 4];
            al[0] = Alu[(g)     * AP32 + ka];
            al[1] = Alu[(g + 8) * AP32 + ka];
            al[2] = Alu[(g)     * AP32 + ka + 4];
            al[3] = Alu[(g + 8) * AP32 + ka + 4];
            unsigned ah2[4], al2[4];
            if (two) {
                ah2[0] = Ahu[(g + 16) * AP32 + ka];
                ah2[1] = Ahu[(g + 24) * AP32 + ka];
                ah2[2] = Ahu[(g + 16) * AP32 + ka + 4];
                ah2[3] = Ahu[(g + 24) * AP32 + ka + 4];
                al2[0] = Alu[(g + 16) * AP32 + ka];
                al2[1] = Alu[(g + 24) * AP32 + ka];
                al2[2] = Alu[(g + 16) * AP32 + ka + 4];
                al2[3] = Alu[(g + 24) * AP32 + ka + 4];
            }

            #pragma unroll
            for (int nt = 0; nt < 4; ++nt) {
                const int n = nb + nt * 8 + g;
                const float w00 = Bb[(2 * lm)     * BPITCH + n];
                const float w01 = Bb[(2 * lm + 1) * BPITCH + n];
                const float w10 = Bb[(2 * lm + 8) * BPITCH + n];
                const float w11 = Bb[(2 * lm + 9) * BPITCH + n];
                unsigned bh0, bl0, bh1, bl1;
                split2(w00, w01, bh0, bl0);
                split2(w10, w11, bh1, bl1);

                mmabf(cacc[0][nt], ah, bh0, bh1);  // hi*hi
                mmabf(cacc[0][nt], al, bh0, bh1);  // lo*hi
                mmabf(cacc[0][nt], ah, bl0, bl1);  // hi*lo
                if (two) {
                    mmabf(cacc[1][nt], ah2, bh0, bh1);
                    mmabf(cacc[1][nt], al2, bh0, bh1);
                    mmabf(cacc[1][nt], ah2, bl0, bl1);
                }
            }
        }

        // ---- store ----
        #pragma unroll
        for (int mt = 0; mt < 2; ++mt) {
            #pragma unroll
            for (int nt = 0; nt < 4; ++nt) {
                const int col = nb + nt * 8 + 2 * lm;
                const int r0 = mc * 32 + mt * 16 + g;
                if (r0 < cnt)
                    *(float2*)(OUT + (size_t)sl[r0] * OUTDIM + col)
                        = make_float2(cacc[mt][nt][0], cacc[mt][nt][1]);
                const int r1 = r0 + 8;
                if (r1 < cnt)
                    *(float2*)(OUT + (size_t)sl[r1] * OUTDIM + col)
                        = make_float2(cacc[mt][nt][2], cacc[mt][nt][3]);
            }
        }
        __syncthreads();                           // guard A smem reuse next chunk
    }
    CP_WAIT0();
}

extern "C" void kernel_launch(void* const* d_in, const int* in_sizes, int n_in,
                              void* d_out, int out_size)
{
    const float* X    = (const float*)d_in[0];
    const void*  TIDS = d_in[1];
    const float* W    = (const float*)d_in[2];
    float*       OUT  = (float*)d_out;

    cudaFuncSetAttribute(tsl_mma, cudaFuncAttributeMaxDynamicSharedMemorySize, DYN_BYTES);
    tsl_mma<<<TASKS, 256, DYN_BYTES>>>(X, TIDS, W, OUT);
}

// round 16
// speedup vs baseline: 1.4827x; 1.0860x over previous
#include <cuda_runtime.h>
#include <cuda_bf16.h>
#include <cstdint>

#define TASKS   128
#define NSAMP   2048
#define INDIM   256
#define OUTDIM  256
#define AP32    132                 // u32 pitch per A row; %32==4 -> conflict-free frags
#define BPITCH  132                 // f32 pitch per B row (128 cols + pad); conflict-free
#define KCH     16
#define NBUF    5
#define AHI_OFF 0
#define ALO_OFF (32 * AP32 * 4)
#define B_OFF   (2 * 32 * AP32 * 4)
#define BBUF_B  (KCH * BPITCH * 4)
#define DYN_BYTES (B_OFF + NBUF * BBUF_B + 16)

__device__ __forceinline__ unsigned smem_u32(const void* p) {
    unsigned r;
    asm("{ .reg .u64 t; cvta.to.shared.u64 t, %1; cvt.u32.u64 %0, t; }" : "=r"(r) : "l"(p));
    return r;
}
// pack two f32 -> bf16x2 (x0 low), plus exact residuals
__device__ __forceinline__ unsigned packbf(float lo, float hi) {
    unsigned r;
    asm("cvt.rn.bf16x2.f32 %0, %1, %2;" : "=r"(r) : "f"(hi), "f"(lo));
    return r;
}
__device__ __forceinline__ void split2(float x0, float x1, unsigned& h, unsigned& l) {
    h = packbf(x0, x1);
    const float h0 = __uint_as_float(h << 16);
    const float h1 = __uint_as_float(h & 0xffff0000u);
    l = packbf(x0 - h0, x1 - h1);
}
__device__ __forceinline__ void mmabf(float (&d)[4], const unsigned (&a)[4],
                                      unsigned b0, unsigned b1) {
    asm volatile(
        "mma.sync.aligned.m16n8k16.row.col.f32.bf16.bf16.f32 "
        "{%0,%1,%2,%3},{%4,%5,%6,%7},{%8,%9},{%0,%1,%2,%3};"
        : "+f"(d[0]), "+f"(d[1]), "+f"(d[2]), "+f"(d[3])
        : "r"(a[0]), "r"(a[1]), "r"(a[2]), "r"(a[3]), "r"(b0), "r"(b1));
}
#define CP16(dst, src) \
    asm volatile("cp.async.cg.shared.global [%0], [%1], 16;" :: "r"(dst), "l"(src) : "memory")
#define CP_COMMIT() asm volatile("cp.async.commit_group;" ::: "memory")
#define CP_WAIT3()  asm volatile("cp.async.wait_group 3;" ::: "memory")
#define CP_WAIT0()  asm volatile("cp.async.wait_group 0;" ::: "memory")

// warps 4-7 stream one 16-row x 128-col (this half) B chunk: 4 CP16 per thread
__device__ __forceinline__ void issueB(const float* __restrict__ Wt, unsigned bbase,
                                       int kc, int tid, int half) {
    if (tid >= 128) {
        const int t = tid - 128, row = t >> 3, cg = t & 7;   // 16 rows x 8 groups of 16 floats
        const float* src = Wt + (size_t)(kc * KCH + row) * OUTDIM + half * 128 + cg * 16;
        const unsigned dst = bbase + (unsigned)(row * BPITCH + cg * 16) * 4u;
        #pragma unroll
        for (int u = 0; u < 4; ++u)
            CP16(dst + 16u * (unsigned)u, src + 4 * u);
    }
}

__global__ __launch_bounds__(256, 2)
void tsl_mma(const float* __restrict__ X, const void* __restrict__ TIDS,
             const float* __restrict__ W, float* __restrict__ OUT)
{
    extern __shared__ __align__(16) char dyn[];
    __shared__ unsigned short sl[NSAMP];
    __shared__ int s_cnt;
    __shared__ unsigned orv;

    const int tid = threadIdx.x, wid = tid >> 5, lane = tid & 31;
    const int g = lane >> 2, lm = lane & 3;
    const int task = blockIdx.x >> 1;
    const int half = blockIdx.x & 1;
    const int nb = wid * 16;                       // warp's 16-col slice within half

    const float* Wt = W + (size_t)task * INDIM * OUTDIM;
    const unsigned bbase0 = smem_u32(dyn + B_OFF);

    if (tid == 0) { s_cnt = 0; orv = 0; }

    // ---- prefetch first 4 B chunks before/while scanning ----
    #pragma unroll
    for (int c = 0; c < 4; ++c) {
        issueB(Wt, bbase0 + (unsigned)c * BBUF_B, c, tid, half);
        CP_COMMIT();
    }
    __syncthreads();

    // ---- ballot-compress scan for this task ----
    const unsigned* w32 = (const unsigned*)TIDS;
    atomicOr(&orv, w32[2 * tid + 1]);              // int64 iff hi words (0..255) all 0
    __syncthreads();
    const bool is64 = (orv == 0);

    #pragma unroll 1
    for (int j = 0; j < 8; ++j) {
        const int n = j * 256 + tid;
        const int id = is64 ? (int)w32[2 * n] : (int)w32[n];
        const bool m = (id == task);
        const unsigned bal = __ballot_sync(0xffffffffu, m);
        if (bal) {
            int b = 0;
            if (lane == 0) b = atomicAdd(&s_cnt, __popc(bal));
            b = __shfl_sync(0xffffffffu, b, 0);
            if (m) sl[b + __popc(bal & ((1u << lane) - 1u))] = (unsigned short)n;
        }
    }
    __syncthreads();
    const int cnt = s_cnt;
    if (cnt == 0) { CP_WAIT0(); return; }

    unsigned* Ahu = (unsigned*)(dyn + AHI_OFF);
    unsigned* Alu = (unsigned*)(dyn + ALO_OFF);

    #pragma unroll 1
    for (int mc = 0; mc * 32 < cnt; ++mc) {
        if (mc > 0) {                              // rare overflow chunk: restream B
            #pragma unroll
            for (int c = 0; c < 4; ++c) {
                issueB(Wt, bbase0 + (unsigned)(c % NBUF) * BBUF_B, c, tid, half);
                CP_COMMIT();
            }
        }
        const bool two = (cnt - mc * 32) > 16;

        // ---- fill A: 32 rows x 256 k as packed bf16x2 hi/lo ----
        {
            const int s = tid >> 3, q = tid & 7;
            const bool valid = (mc * 32 + s < cnt);
            const unsigned srow = valid ? (unsigned)sl[mc * 32 + s] : 0u;
            const float4* xr = (const float4*)(X + srow * INDIM) + q * 8;
            #pragma unroll
            for (int j = 0; j < 8; ++j) {
                float4 v = valid ? __ldg(xr + j) : make_float4(0.f, 0.f, 0.f, 0.f);
                unsigned h0, l0, h1, l1;
                split2(v.x, v.y, h0, l0);
                split2(v.z, v.w, h1, l1);
                const int o = s * AP32 + (q * 8 + j) * 2;
                *(uint2*)(Ahu + o) = make_uint2(h0, h1);
                *(uint2*)(Alu + o) = make_uint2(l0, l1);
            }
        }
        __syncthreads();

        float cacc[2][2][4];
        #pragma unroll
        for (int mt = 0; mt < 2; ++mt)
            #pragma unroll
            for (int nt = 0; nt < 2; ++nt)
                #pragma unroll
                for (int p = 0; p < 4; ++p) cacc[mt][nt][p] = 0.f;

        #pragma unroll 1
        for (int kc = 0; kc < INDIM / KCH; ++kc) {
            CP_WAIT3();
            __syncthreads();                       // also guards buffer (kc+4)%5 reuse
            if (kc + 4 < INDIM / KCH)
                issueB(Wt, bbase0 + (unsigned)((kc + 4) % NBUF) * BBUF_B, kc + 4, tid, half);
            CP_COMMIT();

            const float* Bb = (const float*)(dyn + B_OFF + (kc % NBUF) * BBUF_B);
            const int ka = kc * 8 + lm;

            // A fragments
            unsigned ah[4], al[4], ah2[4], al2[4];
            ah[0] = Ahu[(g)     * AP32 + ka];
            ah[1] = Ahu[(g + 8) * AP32 + ka];
            ah[2] = Ahu[(g)     * AP32 + ka + 4];
            ah[3] = Ahu[(g + 8) * AP32 + ka + 4];
            al[0] = Alu[(g)     * AP32 + ka];
            al[1] = Alu[(g + 8) * AP32 + ka];
            al[2] = Alu[(g)     * AP32 + ka + 4];
            al[3] = Alu[(g + 8) * AP32 + ka + 4];
            if (two) {
                ah2[0] = Ahu[(g + 16) * AP32 + ka];
                ah2[1] = Ahu[(g + 24) * AP32 + ka];
                ah2[2] = Ahu[(g + 16) * AP32 + ka + 4];
                ah2[3] = Ahu[(g + 24) * AP32 + ka + 4];
                al2[0] = Alu[(g + 16) * AP32 + ka];
                al2[1] = Alu[(g + 24) * AP32 + ka];
                al2[2] = Alu[(g + 16) * AP32 + ka + 4];
                al2[3] = Alu[(g + 24) * AP32 + ka + 4];
            }

            // B fragments (2 N-tiles)
            unsigned bh0[2], bl0[2], bh1[2], bl1[2];
            #pragma unroll
            for (int nt = 0; nt < 2; ++nt) {
                const int n = nb + nt * 8 + g;
                const float w00 = Bb[(2 * lm)     * BPITCH + n];
                const float w01 = Bb[(2 * lm + 1) * BPITCH + n];
                const float w10 = Bb[(2 * lm + 8) * BPITCH + n];
                const float w11 = Bb[(2 * lm + 9) * BPITCH + n];
                split2(w00, w01, bh0[nt], bl0[nt]);
                split2(w10, w11, bh1[nt], bl1[nt]);
            }

            // term-outer mma stream: consecutive HMMA hit different accumulators
            mmabf(cacc[0][0], ah, bh0[0], bh1[0]);
            mmabf(cacc[0][1], ah, bh0[1], bh1[1]);
            if (two) {
                mmabf(cacc[1][0], ah2, bh0[0], bh1[0]);
                mmabf(cacc[1][1], ah2, bh0[1], bh1[1]);
            }
            mmabf(cacc[0][0], al, bh0[0], bh1[0]);
            mmabf(cacc[0][1], al, bh0[1], bh1[1]);
            if (two) {
                mmabf(cacc[1][0], al2, bh0[0], bh1[0]);
                mmabf(cacc[1][1], al2, bh0[1], bh1[1]);
            }
            mmabf(cacc[0][0], ah, bl0[0], bl1[0]);
            mmabf(cacc[0][1], ah, bl0[1], bl1[1]);
            if (two) {
                mmabf(cacc[1][0], ah2, bl0[0], bl1[0]);
                mmabf(cacc[1][1], ah2, bl0[1], bl1[1]);
            }
        }

        // ---- store ----
        #pragma unroll
        for (int mt = 0; mt < 2; ++mt) {
            #pragma unroll
            for (int nt = 0; nt < 2; ++nt) {
                const int col = half * 128 + nb + nt * 8 + 2 * lm;
                const int r0 = mc * 32 + mt * 16 + g;
                if (r0 < cnt)
                    *(float2*)(OUT + (size_t)sl[r0] * OUTDIM + col)
                        = make_float2(cacc[mt][nt][0], cacc[mt][nt][1]);
                const int r1 = r0 + 8;
                if (r1 < cnt)
                    *(float2*)(OUT + (size_t)sl[r1] * OUTDIM + col)
                        = make_float2(cacc[mt][nt][2], cacc[mt][nt][3]);
            }
        }
        __syncthreads();                           // guard A smem reuse next chunk
    }
    CP_WAIT0();
}

extern "C" void kernel_launch(void* const* d_in, const int* in_sizes, int n_in,
                              void* d_out, int out_size)
{
    const float* X    = (const float*)d_in[0];
    const void*  TIDS = d_in[1];
    const float* W    = (const float*)d_in[2];
    float*       OUT  = (float*)d_out;

    cudaFuncSetAttribute(tsl_mma, cudaFuncAttributeMaxDynamicSharedMemorySize, DYN_BYTES);
    tsl_mma<<<2 * TASKS, 256, DYN_BYTES>>>(X, TIDS, W, OUT);
}